// round 1
// baseline (speedup 1.0000x reference)
#include <cuda_runtime.h>

#define NN      512
#define TILE    32
#define TG      (NN / TILE)     // 16 tiles per dim
#define BIGV    1e10f
#define SRC_I   256
#define SRC_J   256
#define PASSES  44              // even: result lands back in d_out

#define SU_S    36              // padded row stride for u tile (+halo) in smem

// ping-pong scratch buffer (allowed: __device__ global, no allocation)
__device__ float g_u2[NN * NN];

__device__ __forceinline__ int suidx(int i, int j) { return (i + 1) * SU_S + (j + 1); }

__global__ void eik_init(float* __restrict__ u) {
    int idx = blockIdx.x * blockDim.x + threadIdx.x;
    if (idx < NN * NN) u[idx] = (idx == SRC_I * NN + SRC_J) ? 0.0f : BIGV;
}

// One directional Gauss-Seidel sweep over the 32x32 tile held in smem.
// Diagonal wavefront: at step s, lane t handles logical cell (ii=s-t, jj=t).
// "Updated" neighbors flow through registers (own uprev) and __shfl_up
// (lane t-1's uprev), so the serial chain never round-trips through smem.
template <int DI, int DJ>
__device__ __forceinline__ void sweep_dir(float* su, const float* sfh, const float* sfh2, int t) {
    const int j  = (DJ > 0) ? t : (TILE - 1 - t);
    const int jh = (DJ > 0) ? -1 : TILE;          // halo column for lane 0's left neighbor

    // uprev starts as the i-direction halo value u[i0 - DI][j]
    float uprev = su[suidx((DI > 0) ? -1 : TILE, j)];

#pragma unroll 1
    for (int s = 0; s < 2 * TILE - 1; ++s) {
        const int  ii     = s - t;
        const bool active = (ii >= 0) && (ii < TILE);
        const int  iic    = active ? ii : 0;
        const int  i      = (DI > 0) ? iic : (TILE - 1 - iic);

        // left-new: lane t-1's result from the previous diagonal
        float lft = __shfl_up_sync(0xffffffffu, uprev, 1);
        if (t == 0) lft = su[suidx(i, jh)];       // predicated: only lane 0 loads

        // "old" side neighbors + own old value (current best estimates in smem)
        const float dn_old = su[suidx(i + DI, j)];
        const float rt_old = su[suidx(i, j + DJ)];
        const float oldv   = su[suidx(i, j)];

        const float a   = fminf(uprev, dn_old);   // i-direction upwind min
        const float b   = fminf(lft,   rt_old);   // j-direction upwind min
        const float mn  = fminf(a, b);
        const float mx  = fmaxf(a, b);
        const float d   = mx - mn;
        const float fh  = sfh [i * TILE + j];
        const float fh2 = sfh2[i * TILE + j];     // 2*(f*h)^2, precomputed

        float arg = fmaxf(fmaf(-d, d, fh2), 0.0f);
        float r;
        asm("sqrt.approx.f32 %0, %1;" : "=f"(r) : "f"(arg));

        const float cand = (d >= fh) ? (mn + fh) : (0.5f * ((mn + mx) + r));
        const float nu   = fminf(oldv, cand);

        if (active) {
            su[suidx(i, j)] = nu;
            uprev = nu;
        }
        __syncwarp();   // safety for cross-lane smem old-value reads (round-1 conservative)
    }
}

__global__ __launch_bounds__(TILE) void eik_sweep(const float* __restrict__ src,
                                                  float* __restrict__ dst,
                                                  const float* __restrict__ f) {
    __shared__ float su  [(TILE + 2) * SU_S];
    __shared__ float sfh [TILE * TILE];
    __shared__ float sfh2[TILE * TILE];

    const int t   = threadIdx.x;
    const int bi  = blockIdx.y, bj = blockIdx.x;
    const int gi0 = bi * TILE,  gj0 = bj * TILE;

    // load u tile + 1-cell halo (34x34), BIG outside the domain
#pragma unroll 1
    for (int rr = 0; rr < TILE + 2; ++rr) {
        const int gi = gi0 - 1 + rr;
        const int gj = gj0 - 1 + t;
        const bool rin = (gi >= 0) && (gi < NN);
        float v = (rin && gj >= 0) ? src[gi * NN + gj] : BIGV;
        su[rr * SU_S + t] = v;
        if (t < 2) {
            const int gj2 = gj0 + TILE - 1 + t;   // columns 31..32 of the halo row
            float v2 = (rin && gj2 < NN) ? src[gi * NN + gj2] : BIGV;
            su[rr * SU_S + TILE + t] = v2;
        }
    }
    // slowness tile: fh = f*h (h=1) and 2*fh^2
#pragma unroll 1
    for (int r = 0; r < TILE; ++r) {
        const float fv = f[(gi0 + r) * NN + gj0 + t];
        sfh [r * TILE + t] = fv;
        sfh2[r * TILE + t] = 2.0f * fv * fv;
    }
    __syncwarp();

    // full fast-sweeping cycle: 4 quadrant orderings
    sweep_dir< 1,  1>(su, sfh, sfh2, t);
    sweep_dir< 1, -1>(su, sfh, sfh2, t);
    sweep_dir<-1,  1>(su, sfh, sfh2, t);
    sweep_dir<-1, -1>(su, sfh, sfh2, t);

    // write interior back (ping-pong: full tile every pass)
#pragma unroll 1
    for (int r = 0; r < TILE; ++r)
        dst[(gi0 + r) * NN + gj0 + t] = su[suidx(r, t)];
}

extern "C" void kernel_launch(void* const* d_in, const int* in_sizes, int n_in,
                              void* d_out, int out_size) {
    const float* f = (const float*)d_in[0];
    float* u = (float*)d_out;

    void* p2 = nullptr;
    cudaGetSymbolAddress(&p2, g_u2);
    float* u2 = (float*)p2;

    eik_init<<<(NN * NN + 255) / 256, 256>>>(u);

    dim3 grid(TG, TG);
    for (int p = 0; p < PASSES; ++p) {
        if ((p & 1) == 0) eik_sweep<<<grid, TILE>>>(u,  u2, f);
        else              eik_sweep<<<grid, TILE>>>(u2, u,  f);
    }
    // PASSES is even -> converged result ends in d_out
}

// round 2
// speedup vs baseline: 1.4057x; 1.4057x over previous
#include <cuda_runtime.h>

#define NN      512
#define TILE    32
#define TG      (NN / TILE)
#define BIGV    1e10f
#define SRC_I   256
#define SRC_J   256
#define PASSES  32              // even: result lands back in d_out
#define SU_S    36              // padded row stride for u tile (+halo)

__device__ float g_u2[NN * NN];

__device__ __forceinline__ int suidx(int i, int j) { return (i + 1) * SU_S + (j + 1); }

__global__ void eik_init(float* __restrict__ u) {
    int idx = blockIdx.x * blockDim.x + threadIdx.x;
    if (idx < NN * NN) u[idx] = (idx == SRC_I * NN + SRC_J) ? 0.0f : BIGV;
}

// One directional GS sweep, diagonal wavefront, register-resident neighbors.
// Lane t owns column j. At step s it processes row ii = s - t.
//   - new left neighbor  : __shfl_up of lane t-1's last result (uprev)
//   - old right neighbor : __shfl_down of lane t+1's rolling o_nxt
//   - own old / down-old : rolling registers o_cur / o_nxt
// No smem reads on the critical path; no __syncwarp inside the loop
// (each column has a single writer; cross-lane data moves only via
// *_sync shuffles, which force warp convergence each step).
template <int DI, int DJ>
__device__ __forceinline__ void sweep_dir(float* su, const float* sfh,
                                          const float* sfh2, int t) {
    const int j  = (DJ > 0) ? t : (TILE - 1 - t);
    const int jl = j - DJ;                       // "new" side halo column at edge
    const int jr = j + DJ;                       // "old" side halo column at edge
    const int i0 = (DI > 0) ? 0 : (TILE - 1);

    float uprev = su[suidx(i0 - DI, j)];         // i-direction halo (new side)
    float o_nxt = su[suidx(i0, j)];
    float o_cur = o_nxt;                         // pre-roll (virtual step -1)
    {
        int r = 1 - t; r = (r < 0) ? 0 : r;
        o_nxt = su[suidx(i0 + DI * r, j)];
    }

#pragma unroll 1
    for (int s = 0; s < 2 * TILE - 1; ++s) {
        const int  ii     = s - t;
        const bool active = (ii >= 0) && (ii < TILE);
        const int  iic    = active ? ii : 0;
        const int  i      = i0 + DI * iic;       // physical row (valid even when idle)

        float lft = __shfl_up_sync(0xffffffffu, uprev, 1);
        if (t == 0) lft = su[suidx(i, jl)];
        float rt  = __shfl_down_sync(0xffffffffu, o_nxt, 1);
        if (t == TILE - 1) rt = su[suidx(i, jr)];

        const float a   = fminf(uprev, o_nxt);   // i-direction upwind min
        const float b   = fminf(lft,   rt);      // j-direction upwind min
        const float mn  = fminf(a, b);
        const float d   = fabsf(a - b);
        const float fh  = sfh [i * TILE + j];
        const float fh2 = sfh2[i * TILE + j];    // 2*(f*h)^2
        const float hab = 0.5f * (a + b);

        float arg = fmaxf(fmaf(-d, d, fh2), 0.0f);
        float rq;
        asm("sqrt.approx.f32 %0, %1;" : "=f"(rq) : "f"(arg));

        const float cand = (d >= fh) ? (mn + fh) : fmaf(0.5f, rq, hab);
        const float nu   = fminf(o_cur, cand);

        if (active) {
            su[suidx(i, j)] = nu;                // single writer per column
            uprev = nu;
        }

        // roll the old-value window: o_cur <- old[ii+1], o_nxt <- old[ii+2]
        o_cur = o_nxt;
        int rn = s - t + 2;
        rn = (rn < 0) ? 0 : ((rn > TILE - 1) ? (TILE - 1) : rn);
        o_nxt = su[suidx(i0 + DI * rn, j)];
    }
}

__global__ __launch_bounds__(TILE) void eik_sweep(const float* __restrict__ src,
                                                  float* __restrict__ dst,
                                                  const float* __restrict__ f) {
    __shared__ float su  [(TILE + 2) * SU_S];
    __shared__ float sfh [TILE * TILE];
    __shared__ float sfh2[TILE * TILE];

    const int t   = threadIdx.x;
    const int bi  = blockIdx.y, bj = blockIdx.x;
    const int gi0 = bi * TILE,  gj0 = bj * TILE;

    // u tile + 1-cell halo (34x34); BIG outside the domain
#pragma unroll 1
    for (int rr = 0; rr < TILE + 2; ++rr) {
        const int gi = gi0 - 1 + rr;
        const int gj = gj0 - 1 + t;
        const bool rin = (gi >= 0) && (gi < NN);
        su[rr * SU_S + t] = (rin && gj >= 0) ? src[gi * NN + gj] : BIGV;
        if (t < 2) {
            const int gj2 = gj0 + TILE - 1 + t;
            su[rr * SU_S + TILE + t] = (rin && gj2 < NN) ? src[gi * NN + gj2] : BIGV;
        }
    }
#pragma unroll 1
    for (int r = 0; r < TILE; ++r) {
        const float fv = f[(gi0 + r) * NN + gj0 + t];
        sfh [r * TILE + t] = fv;                 // f*h, h=1
        sfh2[r * TILE + t] = 2.0f * fv * fv;
    }
    __syncwarp();

    sweep_dir< 1,  1>(su, sfh, sfh2, t);  __syncwarp();
    sweep_dir< 1, -1>(su, sfh, sfh2, t);  __syncwarp();
    sweep_dir<-1,  1>(su, sfh, sfh2, t);  __syncwarp();
    sweep_dir<-1, -1>(su, sfh, sfh2, t);  __syncwarp();

#pragma unroll 1
    for (int r = 0; r < TILE; ++r)
        dst[(gi0 + r) * NN + gj0 + t] = su[suidx(r, t)];
}

extern "C" void kernel_launch(void* const* d_in, const int* in_sizes, int n_in,
                              void* d_out, int out_size) {
    const float* f = (const float*)d_in[0];
    float* u = (float*)d_out;

    void* p2 = nullptr;
    cudaGetSymbolAddress(&p2, g_u2);
    float* u2 = (float*)p2;

    eik_init<<<(NN * NN + 255) / 256, 256>>>(u);

    dim3 grid(TG, TG);
    for (int p = 0; p < PASSES; ++p) {
        if ((p & 1) == 0) eik_sweep<<<grid, TILE>>>(u,  u2, f);
        else              eik_sweep<<<grid, TILE>>>(u2, u,  f);
    }
}

// round 5
// speedup vs baseline: 4.7284x; 3.3636x over previous
#include <cuda_runtime.h>

#define NN      512
#define TILE    32
#define TG      (NN / TILE)
#define BIGV    1e10f
#define SRC_I   256
#define SRC_J   256
#define PASSES  32
#define SU_S    36
#define FULLM   0xffffffffu

__device__ float g_u2[NN * NN];

__device__ __forceinline__ int suidx(int i, int j) { return (i + 1) * SU_S + (j + 1); }

__global__ void eik_init(float* __restrict__ u) {
    int idx = blockIdx.x * blockDim.x + threadIdx.x;
    if (idx < NN * NN) u[idx] = (idx == SRC_I * NN + SRC_J) ? 0.0f : BIGV;
}

// One directional GS wavefront over an immutable input tile.
// Lane t owns sweep-column t (physical col j). Step s handles sweep-row ii = s - t
// (physical row i = i0 + DI*ii). Branch-free; merge via unconditional atomicMin.
template <int DI, int DJ>
__device__ __forceinline__ void sweep_dir(const float* __restrict__ su_in,
                                          unsigned*    __restrict__ su_min,
                                          const float2* __restrict__ sf2,
                                          int t) {
    const int j   = (DJ > 0) ? t : (TILE - 1 - t);
    const int jlH = (DJ > 0) ? -1   : TILE;      // new-side halo column (fixed)
    const int jrH = (DJ > 0) ? TILE : -1;        // old-side halo column (fixed)
    const int i0  = (DI > 0) ? 0 : (TILE - 1);

    // lane k holds halo values at sweep-row k (physical row i0 + DI*k)
    const int   irk = i0 + DI * t;
    const float hl  = su_in[suidx(irk, jlH)];
    const float hr  = su_in[suidx(irk, jrH)];

    float uprev = su_in[suidx(i0 - DI, j)];      // new-side i halo
    float o_cur = su_in[suidx(i0, j)];           // old[clamp(ii)]
    int   r1    = (1 - t) > 0 ? (1 - t) : 0;
    float o_nxt = su_in[suidx(i0 + DI * r1, j)]; // old[clamp(ii+1)]
    float2 fv   = sf2[i0 * TILE + j];            // (fh, 2fh^2) at row clamp(ii)

    const bool e0  = (t == 0);
    const bool e31 = (t == TILE - 1);

#pragma unroll 1
    for (int s = 0; s < 2 * TILE - 1; ++s) {
        const int  ii     = s - t;
        const bool active = ((unsigned)ii < (unsigned)TILE);
        const int  iic    = active ? ii : 0;
        const int  i      = i0 + DI * iic;       // PHYSICAL row for the merge

        float lup  = __shfl_up_sync(FULLM, uprev, 1);
        float lftH = __shfl_sync(FULLM, hl, s & 31);          // halo(row s) for lane 0
        float rdn  = __shfl_down_sync(FULLM, o_nxt, 1);
        float rtH  = __shfl_sync(FULLM, hr, (s - 31) & 31);   // halo(row s-31) for lane 31
        const float lft = e0  ? lftH : lup;
        const float rt  = e31 ? rtH  : rdn;

        const float a   = fminf(uprev, o_nxt);
        const float b   = fminf(lft,   rt);
        const float mn  = fminf(a, b);
        const float d   = fabsf(a - b);
        const float hab = 0.5f * (a + b);

        float arg = fmaxf(fmaf(-d, d, fv.y), 0.0f);
        float rq;
        asm("sqrt.approx.f32 %0, %1;" : "=f"(rq) : "f"(arg));

        const float cand = (d >= fv.x) ? (mn + fv.x) : fmaf(0.5f, rq, hab);
        const float nu   = fminf(o_cur, cand);

        const unsigned val = active ? __float_as_uint(nu) : FULLM;
        atomicMin(&su_min[i * TILE + j], val);     // physical (i, j)
        uprev = active ? nu : uprev;

        // roll old-value window + prefetch f for next row
        o_cur = o_nxt;
        int rn = ii + 2; rn = rn < 0 ? 0 : (rn > TILE - 1 ? TILE - 1 : rn);
        o_nxt = su_in[suidx(i0 + DI * rn, j)];
        int rf = ii + 1; rf = rf < 0 ? 0 : (rf > TILE - 1 ? TILE - 1 : rf);
        fv = sf2[(i0 + DI * rf) * TILE + j];
    }
}

__global__ __launch_bounds__(128) void eik_sweep(const float* __restrict__ src,
                                                 float* __restrict__ dst,
                                                 const float* __restrict__ f) {
    __shared__ float    su_in [(TILE + 2) * SU_S];
    __shared__ unsigned su_min[TILE * TILE];
    __shared__ float2   sf2   [TILE * TILE];

    const int tid = threadIdx.x;
    const int w   = tid >> 5;
    const int t   = tid & 31;
    const int gi0 = blockIdx.y * TILE, gj0 = blockIdx.x * TILE;

    // load 34x34 u tile (+halo), BIG outside domain
#pragma unroll 1
    for (int idx = tid; idx < (TILE + 2) * (TILE + 2); idx += 128) {
        const int rr = idx / (TILE + 2);
        const int cc = idx - rr * (TILE + 2);
        const int gi = gi0 - 1 + rr;
        const int gj = gj0 - 1 + cc;
        const bool in = (gi >= 0) && (gi < NN) && (gj >= 0) && (gj < NN);
        su_in[rr * SU_S + cc] = in ? src[gi * NN + gj] : BIGV;
    }
    // slowness tile -> (fh, 2fh^2)
#pragma unroll 1
    for (int idx = tid; idx < TILE * TILE; idx += 128) {
        const int r = idx >> 5, c = idx & 31;
        const float fh = f[(gi0 + r) * NN + gj0 + c];
        sf2[idx] = make_float2(fh, 2.0f * fh * fh);
    }
    __syncthreads();
#pragma unroll 1
    for (int idx = tid; idx < TILE * TILE; idx += 128) {
        const int r = idx >> 5, c = idx & 31;
        su_min[idx] = __float_as_uint(su_in[suidx(r, c)]);
    }
    __syncthreads();

    // 4 quadrant sweeps in parallel, one per warp
    if      (w == 0) sweep_dir< 1,  1>(su_in, su_min, sf2, t);
    else if (w == 1) sweep_dir< 1, -1>(su_in, su_min, sf2, t);
    else if (w == 2) sweep_dir<-1,  1>(su_in, su_min, sf2, t);
    else             sweep_dir<-1, -1>(su_in, su_min, sf2, t);
    __syncthreads();

#pragma unroll 1
    for (int idx = tid; idx < TILE * TILE; idx += 128) {
        const int r = idx >> 5, c = idx & 31;
        dst[(gi0 + r) * NN + gj0 + c] = __uint_as_float(su_min[idx]);
    }
}

extern "C" void kernel_launch(void* const* d_in, const int* in_sizes, int n_in,
                              void* d_out, int out_size) {
    const float* f = (const float*)d_in[0];
    float* u = (float*)d_out;

    void* p2 = nullptr;
    cudaGetSymbolAddress(&p2, g_u2);
    float* u2 = (float*)p2;

    eik_init<<<(NN * NN + 255) / 256, 256>>>(u);

    dim3 grid(TG, TG);
    for (int p = 0; p < PASSES; ++p) {
        if ((p & 1) == 0) eik_sweep<<<grid, 128>>>(u,  u2, f);
        else              eik_sweep<<<grid, 128>>>(u2, u,  f);
    }
}

// round 6
// speedup vs baseline: 6.3885x; 1.3511x over previous
#include <cuda_runtime.h>

#define NN      512
#define TILE    32
#define TG      (NN / TILE)
#define BIGV    1e10f
#define SRC_I   256
#define SRC_J   256
#define PASSES  24
#define SU_S    36
#define FULLM   0xffffffffu
#define WBUF    (TILE * TILE + 1)   // +1 dump slot for idle-lane stores

__device__ float g_u2[NN * NN];

__device__ __forceinline__ int suidx(int i, int j) { return (i + 1) * SU_S + (j + 1); }

__global__ void eik_init(float* __restrict__ u) {
    int idx = blockIdx.x * blockDim.x + threadIdx.x;
    if (idx < NN * NN) u[idx] = (idx == SRC_I * NN + SRC_J) ? 0.0f : BIGV;
}

// One directional GS wavefront over an immutable input tile.
// Lane t owns sweep-column t (physical col j). Step s handles sweep-row ii = s-t.
// Branch-free. Results go to this warp's PRIVATE buffer via plain STS
// (each interior cell written exactly once; idle lanes write the dump slot).
// Halo edge values arrive via broadcast LDS prefetched one step ahead
// (address depends only on s -> N=1 broadcast, no conflict, off-chain).
template <int DI, int DJ>
__device__ __forceinline__ void sweep_dir(const float* __restrict__ su_in,
                                          float*       __restrict__ su_w,
                                          const float2* __restrict__ sf2,
                                          int t) {
    const int j   = (DJ > 0) ? t : (TILE - 1 - t);
    const int jlH = (DJ > 0) ? -1   : TILE;      // new-side halo column (fixed)
    const int jrH = (DJ > 0) ? TILE : -1;        // old-side halo column (fixed)
    const int i0  = (DI > 0) ? 0 : (TILE - 1);
    const bool e0  = (t == 0);
    const bool e31 = (t == TILE - 1);

    float uprev = su_in[suidx(i0 - DI, j)];      // new-side i halo
    float o_cur = su_in[suidx(i0, j)];           // old[clamp(ii)]
    int   r1    = (1 - t) > 0 ? (1 - t) : 0;
    float o_nxt = su_in[suidx(i0 + DI * r1, j)]; // old[clamp(ii+1)]
    float2 fv   = sf2[i0 * TILE + j];            // (fh, 2fh^2) at row clamp(ii)
    float  hl   = su_in[suidx(i0, jlH)];         // new-side halo[clamp(s=0)]
    float  hr   = su_in[suidx(i0, jrH)];         // old-side halo[clamp(s-31)]

#pragma unroll 1
    for (int s = 0; s < 2 * TILE - 1; ++s) {
        const int  ii     = s - t;
        const bool active = ((unsigned)ii < (unsigned)TILE);
        const int  iic    = active ? ii : 0;
        const int  i      = i0 + DI * iic;       // physical row

        float lup = __shfl_up_sync(FULLM, uprev, 1);
        float rdn = __shfl_down_sync(FULLM, o_nxt, 1);
        const float lft = e0  ? hl : lup;
        const float rt  = e31 ? hr : rdn;

        const float a   = fminf(uprev, o_nxt);
        const float b   = fminf(lft,   rt);
        const float mn  = fminf(a, b);
        const float d   = fabsf(a - b);
        const float hab = 0.5f * (a + b);

        float arg = fmaxf(fmaf(-d, d, fv.y), 0.0f);
        float rq;
        asm("sqrt.approx.f32 %0, %1;" : "=f"(rq) : "f"(arg));

        const float cand = (d >= fv.x) ? (mn + fv.x) : fmaf(0.5f, rq, hab);
        const float nu   = fminf(o_cur, cand);

        const int widx = active ? (i * TILE + j) : (TILE * TILE); // dump if idle
        su_w[widx] = nu;                          // plain STS, conflict-free
        uprev = active ? nu : uprev;

        // roll windows + prefetch (all off the critical chain)
        o_cur = o_nxt;
        int rn = ii + 2; rn = rn < 0 ? 0 : (rn > TILE - 1 ? TILE - 1 : rn);
        o_nxt = su_in[suidx(i0 + DI * rn, j)];
        int rf = ii + 1; rf = rf < 0 ? 0 : (rf > TILE - 1 ? TILE - 1 : rf);
        fv = sf2[(i0 + DI * rf) * TILE + j];
        int sh = s + 1; sh = sh > TILE - 1 ? TILE - 1 : sh;
        hl = su_in[suidx(i0 + DI * sh, jlH)];     // broadcast LDS
        int sr = s - 30; sr = sr < 0 ? 0 : (sr > TILE - 1 ? TILE - 1 : sr);
        hr = su_in[suidx(i0 + DI * sr, jrH)];     // broadcast LDS
    }
}

__global__ __launch_bounds__(128) void eik_sweep(const float* __restrict__ src,
                                                 float* __restrict__ dst,
                                                 const float* __restrict__ f) {
    __shared__ float  su_in[(TILE + 2) * SU_S];
    __shared__ float2 sf2  [TILE * TILE];
    __shared__ float  su_w [4][WBUF];             // per-warp private results

    const int tid = threadIdx.x;
    const int w   = tid >> 5;
    const int t   = tid & 31;
    const int gi0 = blockIdx.y * TILE, gj0 = blockIdx.x * TILE;

    // load 34x34 u tile (+halo), BIG outside domain
#pragma unroll 1
    for (int idx = tid; idx < (TILE + 2) * (TILE + 2); idx += 128) {
        const int rr = idx / (TILE + 2);
        const int cc = idx - rr * (TILE + 2);
        const int gi = gi0 - 1 + rr;
        const int gj = gj0 - 1 + cc;
        const bool in = (gi >= 0) && (gi < NN) && (gj >= 0) && (gj < NN);
        su_in[rr * SU_S + cc] = in ? src[gi * NN + gj] : BIGV;
    }
    // slowness tile -> (fh, 2fh^2)
#pragma unroll 1
    for (int idx = tid; idx < TILE * TILE; idx += 128) {
        const int r = idx >> 5, c = idx & 31;
        const float fh = f[(gi0 + r) * NN + gj0 + c];
        sf2[idx] = make_float2(fh, 2.0f * fh * fh);
    }
    __syncthreads();

    // 4 quadrant sweeps in parallel, one per warp, each into its own buffer
    if      (w == 0) sweep_dir< 1,  1>(su_in, su_w[0], sf2, t);
    else if (w == 1) sweep_dir< 1, -1>(su_in, su_w[1], sf2, t);
    else if (w == 2) sweep_dir<-1,  1>(su_in, su_w[2], sf2, t);
    else             sweep_dir<-1, -1>(su_in, su_w[3], sf2, t);
    __syncthreads();

    // 4-way min merge -> dst (every nu already includes min with old value)
#pragma unroll 1
    for (int idx = tid; idx < TILE * TILE; idx += 128) {
        const float v = fminf(fminf(su_w[0][idx], su_w[1][idx]),
                              fminf(su_w[2][idx], su_w[3][idx]));
        const int r = idx >> 5, c = idx & 31;
        dst[(gi0 + r) * NN + gj0 + c] = v;
    }
}

extern "C" void kernel_launch(void* const* d_in, const int* in_sizes, int n_in,
                              void* d_out, int out_size) {
    const float* f = (const float*)d_in[0];
    float* u = (float*)d_out;

    void* p2 = nullptr;
    cudaGetSymbolAddress(&p2, g_u2);
    float* u2 = (float*)p2;

    eik_init<<<(NN * NN + 255) / 256, 256>>>(u);

    dim3 grid(TG, TG);
    for (int p = 0; p < PASSES; ++p) {
        if ((p & 1) == 0) eik_sweep<<<grid, 128>>>(u,  u2, f);
        else              eik_sweep<<<grid, 128>>>(u2, u,  f);
    }
}

// round 7
// speedup vs baseline: 6.5410x; 1.0239x over previous
#include <cuda_runtime.h>

#define NN      512
#define TILE    32
#define TG      (NN / TILE)
#define BIGV    1e10f
#define SRC_I   256
#define SRC_J   256
#define PASSES  20
#define SU_S    36
#define TS      34                  // transposed-tile column stride (even!)
#define FULLM   0xffffffffu
#define WBUF    (TILE * TILE + 2)   // +2 dump slots

__device__ float g_u2[NN * NN];

__device__ __forceinline__ int suidx(int i, int j) { return (i + 1) * SU_S + (j + 1); }

__global__ void eik_init(float* __restrict__ u) {
    int idx = blockIdx.x * blockDim.x + threadIdx.x;
    if (idx < NN * NN) u[idx] = (idx == SRC_I * NN + SRC_J) ? 0.0f : BIGV;
}

__device__ __forceinline__ float god(float a, float b, float fh, float fh2, float o) {
    const float mn  = fminf(a, b);
    const float d   = fabsf(a - b);
    const float arg = fmaxf(fmaf(-d, d, fh2), 0.0f);
    float rq;
    asm("sqrt.approx.f32 %0, %1;" : "=f"(rq) : "f"(arg));
    const float cand = (d >= fh) ? (mn + fh) : fmaf(0.5f, rq, 0.5f * (a + b));
    return fminf(o, cand);
}

// load a (sweep-ordered) row pair p from a dense physical-row array
template <int DI>
__device__ __forceinline__ float2 load_pair(const float* base, int p) {
    const int idx = (DI > 0) ? (2 * p) : (30 - 2 * p);
    float2 v = *reinterpret_cast<const float2*>(base + idx);   // 8B-aligned
    return (DI > 0) ? v : make_float2(v.y, v.x);
}
template <int DI>
__device__ __forceinline__ float4 load_fpair(const float2* col, int p) {
    const int idx = (DI > 0) ? (2 * p) : (30 - 2 * p);
    float4 v = *reinterpret_cast<const float4*>(col + idx);    // 16B-aligned
    return (DI > 0) ? v : make_float4(v.z, v.w, v.x, v.y);
}

// Directional GS wavefront, 2 rows per lane per step (47 steps).
// Lane t owns physical column j. Step s handles sweep-row pair ii = s-t
// (sweep rows 2ii, 2ii+1). Branch-free; all old-value feeds vectorized.
template <int DI, int DJ>
__device__ __forceinline__ void sweep_dir(const float* __restrict__ su_in,
                                          const float* __restrict__ su_T,
                                          const float* __restrict__ hcL,
                                          const float* __restrict__ hcR,
                                          const float2* __restrict__ sfT,
                                          float* __restrict__ su_w, int t) {
    const int j  = (DJ > 0) ? t : (TILE - 1 - t);
    const int i0 = (DI > 0) ? 0 : (TILE - 1);
    const bool e0  = (t == 0);
    const bool e31 = (t == TILE - 1);

    const float*  hN   = (DJ > 0) ? hcL : hcR;   // new-side halo column
    const float*  hO   = (DJ > 0) ? hcR : hcL;   // old-side halo column
    const float*  colT = su_T + j * TS;
    const float2* colF = sfT  + j * TS;

    // init: prev1 = i-direction halo; windows at pair 0 / clamp(1-t)
    float prev1 = su_in[suidx(i0 - DI, j)];
    float prev0 = prev1;
    float2 ocv = load_pair<DI>(colT, 0);
    float oc0 = ocv.x, oc1 = ocv.y;
    float2 onv = load_pair<DI>(colT, (t == 0) ? 1 : 0);
    float on0 = onv.x, on1 = onv.y;
    float4 fvv = load_fpair<DI>(colF, 0);
    float fx0 = fvv.x, fy0 = fvv.y, fx1 = fvv.z, fy1 = fvv.w;
    float2 hlv = load_pair<DI>(hN, 0);
    float hl0 = hlv.x, hl1 = hlv.y;
    float2 hrv = load_pair<DI>(hO, 0);
    float hr0 = hrv.x, hr1 = hrv.y;

#pragma unroll 1
    for (int s = 0; s < TILE + TILE / 2 - 1; ++s) {            // 47 steps
        const int  ii     = s - t;
        const bool active = ((unsigned)ii < (unsigned)(TILE / 2));
        const int  iic    = active ? ii : 0;

        const float l0 = __shfl_up_sync(FULLM, prev0, 1);
        const float l1 = __shfl_up_sync(FULLM, prev1, 1);
        const float r0 = __shfl_down_sync(FULLM, on0, 1);
        const float r1 = __shfl_down_sync(FULLM, on1, 1);
        const float lft0 = e0  ? hl0 : l0;
        const float lft1 = e0  ? hl1 : l1;
        const float rt0  = e31 ? hr0 : r0;
        const float rt1  = e31 ? hr1 : r1;

        // cell r0 = sweep row 2ii : up-new = prev1, down-old = oc1
        const float a0 = fminf(prev1, oc1);
        const float b0 = fminf(lft0, rt0);
        const float nu0 = god(a0, b0, fx0, fy0, oc0);
        // cell r1 = sweep row 2ii+1 : up-new = nu0, down-old = on0 (old 2ii+2)
        const float a1 = fminf(nu0, on0);
        const float b1 = fminf(lft1, rt1);
        const float nu1 = god(a1, b1, fx1, fy1, oc1);

        const int ir0 = (DI > 0) ? (2 * iic)     : (TILE - 1 - 2 * iic);
        const int ir1 = (DI > 0) ? (2 * iic + 1) : (TILE - 2 - 2 * iic);
        su_w[active ? (ir0 * TILE + j) : (TILE * TILE)]     = nu0;
        su_w[active ? (ir1 * TILE + j) : (TILE * TILE + 1)] = nu1;
        prev0 = active ? nu0 : prev0;
        prev1 = active ? nu1 : prev1;

        // roll + prefetch (all clamped reads only over-estimate -> safe)
        oc0 = on0; oc1 = on1;
        int pn = ii + 2; pn = pn < 0 ? 0 : (pn > 15 ? 15 : pn);
        onv = load_pair<DI>(colT, pn); on0 = onv.x; on1 = onv.y;
        int pf = ii + 1; pf = pf < 0 ? 0 : (pf > 15 ? 15 : pf);
        fvv = load_fpair<DI>(colF, pf);
        fx0 = fvv.x; fy0 = fvv.y; fx1 = fvv.z; fy1 = fvv.w;
        int ph = s + 1; ph = ph > 15 ? 15 : ph;
        hlv = load_pair<DI>(hN, ph); hl0 = hlv.x; hl1 = hlv.y;
        int pr = s - 30; pr = pr < 0 ? 0 : (pr > 15 ? 15 : pr);
        hrv = load_pair<DI>(hO, pr); hr0 = hrv.x; hr1 = hrv.y;
    }
}

__global__ __launch_bounds__(128) void eik_sweep(const float* __restrict__ src,
                                                 float* __restrict__ dst,
                                                 const float* __restrict__ f) {
    __shared__ alignas(16) float  su_in[(TILE + 2) * SU_S];
    __shared__ alignas(16) float  su_T [TILE * TS];       // su_T[j*TS + i]
    __shared__ alignas(16) float  hcL[TILE], hcR[TILE];   // halo columns
    __shared__ alignas(16) float2 sfT [TILE * TS];        // (fh, 2fh^2), col-major
    __shared__ float su_w[4][WBUF];

    const int tid = threadIdx.x;
    const int w   = tid >> 5;
    const int t   = tid & 31;
    const int gi0 = blockIdx.y * TILE, gj0 = blockIdx.x * TILE;

    // phase 1: 34x34 u tile (+halo) from global
#pragma unroll 1
    for (int idx = tid; idx < (TILE + 2) * (TILE + 2); idx += 128) {
        const int rr = idx / (TILE + 2);
        const int cc = idx - rr * (TILE + 2);
        const int gi = gi0 - 1 + rr;
        const int gj = gj0 - 1 + cc;
        const bool in = (gi >= 0) && (gi < NN) && (gj >= 0) && (gj < NN);
        su_in[rr * SU_S + cc] = in ? src[gi * NN + gj] : BIGV;
    }
    __syncthreads();
    // phase 2: transposed u tile, halo columns, column-major slowness
#pragma unroll 1
    for (int idx = tid; idx < TILE * TILE; idx += 128) {
        const int r = idx >> 5, c = idx & 31;
        su_T[c * TS + r] = su_in[suidx(r, c)];
        const float fh = f[(gi0 + r) * NN + gj0 + c];
        sfT[c * TS + r] = make_float2(fh, 2.0f * fh * fh);
    }
    if (tid < TILE) {
        hcL[tid] = su_in[suidx(tid, -1)];
        hcR[tid] = su_in[suidx(tid, TILE)];
    }
    __syncthreads();

    if      (w == 0) sweep_dir< 1,  1>(su_in, su_T, hcL, hcR, sfT, su_w[0], t);
    else if (w == 1) sweep_dir< 1, -1>(su_in, su_T, hcL, hcR, sfT, su_w[1], t);
    else if (w == 2) sweep_dir<-1,  1>(su_in, su_T, hcL, hcR, sfT, su_w[2], t);
    else             sweep_dir<-1, -1>(su_in, su_T, hcL, hcR, sfT, su_w[3], t);
    __syncthreads();

#pragma unroll 1
    for (int idx = tid; idx < TILE * TILE; idx += 128) {
        const float v = fminf(fminf(su_w[0][idx], su_w[1][idx]),
                              fminf(su_w[2][idx], su_w[3][idx]));
        const int r = idx >> 5, c = idx & 31;
        dst[(gi0 + r) * NN + gj0 + c] = v;
    }
}

extern "C" void kernel_launch(void* const* d_in, const int* in_sizes, int n_in,
                              void* d_out, int out_size) {
    const float* f = (const float*)d_in[0];
    float* u = (float*)d_out;

    void* p2 = nullptr;
    cudaGetSymbolAddress(&p2, g_u2);
    float* u2 = (float*)p2;

    eik_init<<<(NN * NN + 255) / 256, 256>>>(u);

    dim3 grid(TG, TG);
    for (int p = 0; p < PASSES; ++p) {
        if ((p & 1) == 0) eik_sweep<<<grid, 128>>>(u,  u2, f);
        else              eik_sweep<<<grid, 128>>>(u2, u,  f);
    }
}